// round 14
// baseline (speedup 1.0000x reference)
#include <cuda_runtime.h>
#include <cstdint>

typedef unsigned long long ull;

#define NPTS 16384
#define NPER 8192
#define MQ   4096
#define OD   256
#define CG   131
#define CGP  132   // padded loop trip (row 131 zeroed)

// ---------------- device scratch (no runtime allocation allowed) -------------
__device__ float g_featsT[NPTS * 128];        // [point][channel]
__device__ float g_keyT[(CG + 8) * OD];       // [c][o], zero-padded rows
__device__ float g_v1T [(CG + 8) * OD];
__device__ float g_v2T [(OD + 8) * OD];
__device__ float g_ctx4[OD * OD * 4];         // [c][o][{vc,qc,kc,qkc}]
__device__ float g_gate4[64 * 256 * 4];       // [c4][col(cls|reg)][4 c]
__device__ int   g_idx [MQ * 32];

// ---------------- packed fp32x2 helpers --------------------------------------
__device__ __forceinline__ void ffma2(ull& d, ull a, ull b) {
    asm("fma.rn.f32x2 %0, %1, %2, %0;" : "+l"(d) : "l"(a), "l"(b));
}
__device__ __forceinline__ ull pack2(float x) {
    ull r; unsigned xi = __float_as_uint(x);
    asm("mov.b64 %0, {%1, %2};" : "=l"(r) : "r"(xi), "r"(xi));
    return r;
}
__device__ __forceinline__ float2 unpack2(ull v) {
    unsigned lo, hi;
    asm("mov.b64 {%0, %1}, %2;" : "=r"(lo), "=r"(hi) : "l"(v));
    return make_float2(__uint_as_float(lo), __uint_as_float(hi));
}
__device__ __forceinline__ float sigf(float x) { return 1.f / (1.f + expf(-x)); }

// ---------------- weight prep ------------------------------------------------
__global__ void wprep_kernel(const float* __restrict__ key_w, const float* __restrict__ v1w,
                             const float* __restrict__ v2w,  const float* __restrict__ kcw,
                             const float* __restrict__ qcw,  const float* __restrict__ qkcw,
                             const float* __restrict__ vcw,  const float* __restrict__ cw1,
                             const float* __restrict__ rw1) {
    int i = blockIdx.x * 256 + threadIdx.x;        // 65536 total
    if (i < OD * OD) {
        int c = i >> 8, o = i & 255;
        g_v2T[i] = v2w[o * OD + c];
        float4 cv = make_float4(vcw[o * OD + c], qcw[o * OD + c],
                                kcw[o * OD + c], qkcw[o * OD + c]);
        *(float4*)(g_ctx4 + (size_t)i * 4) = cv;
    }
    if (i < CG * OD) {
        int c = i >> 8, o = i & 255;
        g_keyT[i] = key_w[o * CG + c];
        g_v1T[i]  = v1w[o * CG + c];
    }
    if (i < 64 * 256) {
        int c4 = i >> 8, col = i & 255;
        const float* src = (col < 128) ? cw1 : rw1;
        int t = col & 127;
        float4 v = make_float4(src[t * OD + c4 * 4],     src[t * OD + c4 * 4 + 1],
                               src[t * OD + c4 * 4 + 2], src[t * OD + c4 * 4 + 3]);
        *(float4*)(g_gate4 + (size_t)i * 4) = v;
    }
}

// ---------------- feature transpose ------------------------------------------
__global__ void tfeat_kernel(const float* __restrict__ f) {
    __shared__ float t[32][33];
    int b = blockIdx.z, ct = blockIdx.y * 32, nt = blockIdx.x * 32;
    int x = threadIdx.x, y = threadIdx.y;
    #pragma unroll
    for (int r = 0; r < 32; r += 8)
        t[y + r][x] = f[((size_t)(b * 128 + ct + y + r)) * NPER + nt + x];
    __syncthreads();
    #pragma unroll
    for (int r = 0; r < 32; r += 8)
        g_featsT[(size_t)(b * NPER + nt + y + r) * 128 + ct + x] = t[x][y + r];
}

// ---------------- ball query -------------------------------------------------
__global__ __launch_bounds__(256) void ball_kernel(const float* __restrict__ xyz,
                                                   const float* __restrict__ nxyz) {
    __shared__ int sbuf[8][32];
    int warp = threadIdx.x >> 5, lane = threadIdx.x & 31;
    int m = blockIdx.x * 8 + warp;
    float r2 = __fmul_rn(1.6f, 1.6f);
    float qx = nxyz[m * 3 + 0], qy = nxyz[m * 3 + 1], qz = nxyz[m * 3 + 2];
    int count = 0;
    for (int base = 0; base < NPTS; base += 32) {
        int p = base + lane;
        float dx = __fadd_rn(xyz[p * 3 + 0], -qx);
        float dy = __fadd_rn(xyz[p * 3 + 1], -qy);
        float dz = __fadd_rn(xyz[p * 3 + 2], -qz);
        float d2 = __fadd_rn(__fadd_rn(__fmul_rn(dx, dx), __fmul_rn(dy, dy)),
                             __fmul_rn(dz, dz));
        unsigned msk = __ballot_sync(0xffffffffu, d2 < r2);
        int slot = count + __popc(msk & ((1u << lane) - 1u));
        if ((msk >> lane & 1u) && slot < 32) sbuf[warp][slot] = p;
        count += __popc(msk);
        if (count >= 32) break;
    }
    __syncwarp();
    int v = 0;
    if (count > 0) v = (lane < count) ? sbuf[warp][lane] : sbuf[warp][0];
    g_idx[m * 32 + lane] = v;
}

// ---------------- main fused kernel ------------------------------------------
// smem float offsets
#define OFF_GF   0        // 132*32 (row 131 zero pad)
#define OFF_VB   4224     // 256*32, col-rotated
#define OFF_PMH  12416    // 2*256
#define OFF_KMH  12928
#define OFF_PKH  13440
#define OFF_MI4  13952    // 256*4 {pm,km,pkm,0}
#define OFF_CTX  14976    // 4*256
#define OFF_AWI  16000    // 256*4
#define OFF_PART 17024    // 8*128
#define OFF_ATT  18048    // 4*32
#define OFF_NFH  18176    // 2*256
#define OFF_NF   18688    // 256
#define OFF_HID  18944    // 256
#define OFF_MISC 19200    // q(0..2), gates(4,5), idx ints at +8
#define SM_FLOATS 19248
#define BNS 0.99999500003749987f

// GEMM pass: 8o x 4n per thread, o-packed accumulators, prefetch ring depth 4.
__device__ __forceinline__ void gemm_pass(const float* __restrict__ wbase,
                                          const float* __restrict__ smem,
                                          int n_base, int trip, bool rot,
                                          ull acc[4][4]) {
    const ulonglong2* wb = (const ulonglong2*)wbase;
    ulonglong2 wr[4][2];
    #pragma unroll
    for (int i = 0; i < 4; i++) {
        wr[i][0] = __ldg(wb + i * 64);
        wr[i][1] = __ldg(wb + i * 64 + 1);
    }
    #pragma unroll 1
    for (int cb = 0; cb < trip; cb += 4) {
        #pragma unroll
        for (int s = 0; s < 4; s++) {
            int c = cb + s;
            ulonglong2 w0 = wr[s][0], w1 = wr[s][1];
            wr[s][0] = __ldg(wb + (c + 4) * 64);
            wr[s][1] = __ldg(wb + (c + 4) * 64 + 1);
            int col = rot ? ((n_base + (((c >> 3) & 7) << 2)) & 31) : n_base;
            float4 g = *(const float4*)(smem + c * 32 + col);
            ull b0 = pack2(g.x), b1 = pack2(g.y), b2 = pack2(g.z), b3 = pack2(g.w);
            ffma2(acc[0][0], w0.x, b0); ffma2(acc[0][1], w0.x, b1);
            ffma2(acc[0][2], w0.x, b2); ffma2(acc[0][3], w0.x, b3);
            ffma2(acc[1][0], w0.y, b0); ffma2(acc[1][1], w0.y, b1);
            ffma2(acc[1][2], w0.y, b2); ffma2(acc[1][3], w0.y, b3);
            ffma2(acc[2][0], w1.x, b0); ffma2(acc[2][1], w1.x, b1);
            ffma2(acc[2][2], w1.x, b2); ffma2(acc[2][3], w1.x, b3);
            ffma2(acc[3][0], w1.y, b0); ffma2(acc[3][1], w1.y, b1);
            ffma2(acc[3][2], w1.y, b2); ffma2(acc[3][3], w1.y, b3);
        }
    }
}

__global__ __launch_bounds__(256, 2) void main_kernel(
    const float* __restrict__ xyz,  const float* __restrict__ nxyz,
    const float* __restrict__ pos_w,
    const float* __restrict__ bn1g, const float* __restrict__ bn1b,
    const float* __restrict__ bn2g, const float* __restrict__ bn2b,
    const float* __restrict__ attn_w,
    const float* __restrict__ cb1,  const float* __restrict__ cw2,
    const float* __restrict__ cb2,  const float* __restrict__ rb1,
    const float* __restrict__ rw2,  const float* __restrict__ rb2,
    float* __restrict__ out)
{
    extern __shared__ float sm[];
    const int m = blockIdx.x, tid = threadIdx.x;
    const int l = tid & 31, w = tid >> 5;
    int* sidx = (int*)(sm + OFF_MISC + 8);
    if (tid < 32) sidx[tid] = g_idx[m * 32 + tid];
    if (tid >= 32 && tid < 35) sm[OFF_MISC + tid - 32] = nxyz[m * 3 + tid - 32];
    if (tid >= 64 && tid < 96) sm[OFF_GF + 131 * 32 + (tid - 64)] = 0.f;  // pad row
    #pragma unroll
    for (int h = 0; h < 4; h++) sm[OFF_AWI + tid * 4 + h] = __ldg(attn_w + h * 256 + tid);
    __syncthreads();

    // ---- gather gf = [gx(3) ; feats(128)] rows, plain [c][n] layout ----
    {
        int part = tid >> 5, n = tid & 31;
        int p = sidx[n];
        const float4* src = (const float4*)(g_featsT + (size_t)p * 128 + part * 16);
        #pragma unroll
        for (int k = 0; k < 4; k++) {
            float4 v = __ldg(src + k);
            int c = 3 + part * 16 + k * 4;
            sm[OFF_GF + c * 32 + n]       = v.x;
            sm[OFF_GF + (c + 1) * 32 + n] = v.y;
            sm[OFF_GF + (c + 2) * 32 + n] = v.z;
            sm[OFF_GF + (c + 3) * 32 + n] = v.w;
        }
        if (part == 0) {
            float qx = sm[OFF_MISC], qy = sm[OFF_MISC + 1], qz = sm[OFF_MISC + 2];
            sm[OFF_GF + n]      = xyz[p * 3 + 0] - qx;
            sm[OFF_GF + 32 + n] = xyz[p * 3 + 1] - qy;
            sm[OFF_GF + 64 + n] = xyz[p * 3 + 2] - qz;
        }
    }
    __syncthreads();

    // thread tile: 8o x 4n. warp covers 64o x 16n.
    const int og = l & 7, ng = l >> 3;
    const int o_base = (w & 3) * 64 + og * 8;
    const int n_base = (w >> 2) * 16 + ng * 4;
    const int colw = (n_base + og * 4) & 31;     // rotated col for own rows

    // ---- pass A: key ----
    ull acc[4][4];
    #pragma unroll
    for (int i = 0; i < 4; i++)
        #pragma unroll
        for (int j = 0; j < 4; j++) acc[i][j] = 0ull;
    gemm_pass(g_keyT + o_base, sm + OFF_GF, n_base, CGP, false, acc);
    float key_f[8][4];
    #pragma unroll
    for (int i = 0; i < 4; i++)
        #pragma unroll
        for (int j = 0; j < 4; j++) {
            float2 u = unpack2(acc[i][j]);
            key_f[2 * i][j]     = fmaxf(u.x, 0.f);
            key_f[2 * i + 1][j] = fmaxf(u.y, 0.f);
        }

    // ---- pass B: val1 ----
    #pragma unroll
    for (int i = 0; i < 4; i++)
        #pragma unroll
        for (int j = 0; j < 4; j++) acc[i][j] = 0ull;
    gemm_pass(g_v1T + o_base, sm + OFF_GF, n_base, CGP, false, acc);

    // ---- epilogue 1: v -> VB (rotated), means partials ----
    {
        float4 g1a = __ldg((const float4*)(bn1g + o_base));
        float4 g1b = __ldg((const float4*)(bn1g + o_base + 4));
        float4 b1a = __ldg((const float4*)(bn1b + o_base));
        float4 b1b = __ldg((const float4*)(bn1b + o_base + 4));
        float g1[8] = {g1a.x, g1a.y, g1a.z, g1a.w, g1b.x, g1b.y, g1b.z, g1b.w};
        float b1[8] = {b1a.x, b1a.y, b1a.z, b1a.w, b1b.x, b1b.y, b1b.z, b1b.w};
        float v_f[8][4];
        #pragma unroll
        for (int i = 0; i < 4; i++)
            #pragma unroll
            for (int j = 0; j < 4; j++) {
                float2 u = unpack2(acc[i][j]);
                v_f[2 * i][j]     = fmaxf(fmaf(g1[2 * i],     u.x * BNS, b1[2 * i]),     0.f);
                v_f[2 * i + 1][j] = fmaxf(fmaf(g1[2 * i + 1], u.y * BNS, b1[2 * i + 1]), 0.f);
            }
        #pragma unroll
        for (int i = 0; i < 8; i++)
            *(float4*)(sm + OFF_VB + (o_base + i) * 32 + colw) =
                make_float4(v_f[i][0], v_f[i][1], v_f[i][2], v_f[i][3]);

        // pos recompute + means over this thread's 4 n
        float4 x0 = *(const float4*)(sm + OFF_GF + 0 * 32 + n_base);
        float4 x1 = *(const float4*)(sm + OFF_GF + 1 * 32 + n_base);
        float4 x2 = *(const float4*)(sm + OFF_GF + 2 * 32 + n_base);
        float gx0[4] = {x0.x, x0.y, x0.z, x0.w};
        float gx1[4] = {x1.x, x1.y, x1.z, x1.w};
        float gx2[4] = {x2.x, x2.y, x2.z, x2.w};
        float4 pwq[6];
        #pragma unroll
        for (int i = 0; i < 6; i++) pwq[i] = __ldg((const float4*)(pos_w + o_base * 3) + i);
        float pf[24];
        #pragma unroll
        for (int i = 0; i < 6; i++) {
            pf[4 * i] = pwq[i].x; pf[4 * i + 1] = pwq[i].y;
            pf[4 * i + 2] = pwq[i].z; pf[4 * i + 3] = pwq[i].w;
        }
        float ps[8], ks[8], pks[8];
        #pragma unroll
        for (int i = 0; i < 8; i++) {
            float a = 0.f, b = 0.f, c2 = 0.f;
            #pragma unroll
            for (int j = 0; j < 4; j++) {
                float pn = fmaxf(fmaf(pf[3 * i], gx0[j],
                              fmaf(pf[3 * i + 1], gx1[j], pf[3 * i + 2] * gx2[j])), 0.f);
                a += pn; b += key_f[i][j]; c2 += pn * key_f[i][j];
            }
            ps[i] = a; ks[i] = b; pks[i] = c2;
        }
        #pragma unroll
        for (int i = 0; i < 8; i++) {
            #pragma unroll
            for (int d = 8; d <= 16; d <<= 1) {
                ps[i]  += __shfl_xor_sync(~0u, ps[i],  d);
                ks[i]  += __shfl_xor_sync(~0u, ks[i],  d);
                pks[i] += __shfl_xor_sync(~0u, pks[i], d);
            }
        }
        if (ng == 0) {
            int hb = (w >> 2) * 256;
            *(float4*)(sm + OFF_PMH + hb + o_base)     = make_float4(ps[0], ps[1], ps[2], ps[3]);
            *(float4*)(sm + OFF_PMH + hb + o_base + 4) = make_float4(ps[4], ps[5], ps[6], ps[7]);
            *(float4*)(sm + OFF_KMH + hb + o_base)     = make_float4(ks[0], ks[1], ks[2], ks[3]);
            *(float4*)(sm + OFF_KMH + hb + o_base + 4) = make_float4(ks[4], ks[5], ks[6], ks[7]);
            *(float4*)(sm + OFF_PKH + hb + o_base)     = make_float4(pks[0], pks[1], pks[2], pks[3]);
            *(float4*)(sm + OFF_PKH + hb + o_base + 4) = make_float4(pks[4], pks[5], pks[6], pks[7]);
        }
    }
    __syncthreads();

    // ---- combine mean halves ----
    {
        float pm = (sm[OFF_PMH + tid] + sm[OFF_PMH + 256 + tid]) * (1.f / 32.f);
        float km = (sm[OFF_KMH + tid] + sm[OFF_KMH + 256 + tid]) * (1.f / 32.f);
        float pk = (sm[OFF_PKH + tid] + sm[OFF_PKH + 256 + tid]) * (1.f / 32.f);
        *(float4*)(sm + OFF_MI4 + tid * 4) = make_float4(pm, km, pk, 0.f);
    }
    __syncthreads();

    // ---- ctx matvecs ----
    {
        float av = 0.f, aq = 0.f, ak = 0.f, aqk = 0.f;
        const float4* cw = (const float4*)g_ctx4;
        #pragma unroll 8
        for (int c = 0; c < OD; c++) {
            float4 wv = __ldg(cw + c * 256 + tid);
            float4 mi = *(const float4*)(sm + OFF_MI4 + c * 4);
            av  = fmaf(mi.x, wv.x, av);
            aq  = fmaf(mi.x, wv.y, aq);
            ak  = fmaf(mi.y, wv.z, ak);
            aqk = fmaf(mi.z, wv.w, aqk);
        }
        sm[OFF_CTX + tid]       = sigf(av);
        sm[OFF_CTX + 256 + tid] = sigf(aq);
        sm[OFF_CTX + 512 + tid] = sigf(ak);
        sm[OFF_CTX + 768 + tid] = sigf(aqk);
    }

    // ---- val2 GEMM ----
    #pragma unroll
    for (int i = 0; i < 4; i++)
        #pragma unroll
        for (int j = 0; j < 4; j++) acc[i][j] = 0ull;
    gemm_pass(g_v2T + o_base, sm + OFF_VB, n_base, OD, true, acc);
    __syncthreads();   // VB reads done everywhere; CTX visible

    // ---- epilogue 2: val regs + attn_emb -> VB (rotated) ----
    float val_f[8][4];
    {
        float4 g2a = __ldg((const float4*)(bn2g + o_base));
        float4 g2b = __ldg((const float4*)(bn2g + o_base + 4));
        float4 b2a = __ldg((const float4*)(bn2b + o_base));
        float4 b2b = __ldg((const float4*)(bn2b + o_base + 4));
        float g2[8] = {g2a.x, g2a.y, g2a.z, g2a.w, g2b.x, g2b.y, g2b.z, g2b.w};
        float b2[8] = {b2a.x, b2a.y, b2a.z, b2a.w, b2b.x, b2b.y, b2b.z, b2b.w};
        float4 v0 = *(const float4*)(sm + OFF_CTX + o_base);
        float4 v1 = *(const float4*)(sm + OFF_CTX + o_base + 4);
        float4 q0 = *(const float4*)(sm + OFF_CTX + 256 + o_base);
        float4 q1 = *(const float4*)(sm + OFF_CTX + 256 + o_base + 4);
        float4 k0 = *(const float4*)(sm + OFF_CTX + 512 + o_base);
        float4 k1 = *(const float4*)(sm + OFF_CTX + 512 + o_base + 4);
        float4 u0 = *(const float4*)(sm + OFF_CTX + 768 + o_base);
        float4 u1 = *(const float4*)(sm + OFF_CTX + 768 + o_base + 4);
        float vc[8]  = {v0.x, v0.y, v0.z, v0.w, v1.x, v1.y, v1.z, v1.w};
        float qc[8]  = {q0.x, q0.y, q0.z, q0.w, q1.x, q1.y, q1.z, q1.w};
        float kc[8]  = {k0.x, k0.y, k0.z, k0.w, k1.x, k1.y, k1.z, k1.w};
        float qkc[8] = {u0.x, u0.y, u0.z, u0.w, u1.x, u1.y, u1.z, u1.w};
        float4 x0 = *(const float4*)(sm + OFF_GF + 0 * 32 + n_base);
        float4 x1 = *(const float4*)(sm + OFF_GF + 1 * 32 + n_base);
        float4 x2 = *(const float4*)(sm + OFF_GF + 2 * 32 + n_base);
        float gx0[4] = {x0.x, x0.y, x0.z, x0.w};
        float gx1[4] = {x1.x, x1.y, x1.z, x1.w};
        float gx2[4] = {x2.x, x2.y, x2.z, x2.w};
        float4 pwq[6];
        #pragma unroll
        for (int i = 0; i < 6; i++) pwq[i] = __ldg((const float4*)(pos_w + o_base * 3) + i);
        float pf[24];
        #pragma unroll
        for (int i = 0; i < 6; i++) {
            pf[4 * i] = pwq[i].x; pf[4 * i + 1] = pwq[i].y;
            pf[4 * i + 2] = pwq[i].z; pf[4 * i + 3] = pwq[i].w;
        }
        #pragma unroll
        for (int i = 0; i < 8; i++) {
            float raw[4];
            {
                float2 a = unpack2(acc[i >> 1][0]);  // placeholder; replaced below
                (void)a;
            }
            #pragma unroll
            for (int j = 0; j < 4; j++) {
                float2 u = unpack2(acc[i >> 1][j]);
                raw[j] = (i & 1) ? u.y : u.x;
            }
            float emb[4];
            #pragma unroll
            for (int j = 0; j < 4; j++) {
                float pn = fmaxf(fmaf(pf[3 * i], gx0[j],
                              fmaf(pf[3 * i + 1], gx1[j], pf[3 * i + 2] * gx2[j])), 0.f);
                val_f[i][j] = fmaxf(fmaf(g2[i], raw[j] * BNS, b2[i]), 0.f) + pn * vc[i];
                emb[j] = fmaf(pn, qc[i],
                          fmaf(key_f[i][j], kc[i], (pn * key_f[i][j]) * qkc[i]));
            }
            *(float4*)(sm + OFF_VB + (o_base + i) * 32 + colw) =
                make_float4(emb[0], emb[1], emb[2], emb[3]);
        }
    }
    __syncthreads();

    // ---- logits partials: warp w covers rows [w*32, w*32+32) ----
    {
        float a0 = 0.f, a1 = 0.f, a2 = 0.f, a3 = 0.f;
        #pragma unroll 4
        for (int c = w * 32; c < w * 32 + 32; c++) {
            int col = (l + (((c >> 3) & 7) << 2)) & 31;
            float x = sm[OFF_VB + c * 32 + col];
            float4 aw = *(const float4*)(sm + OFF_AWI + c * 4);
            a0 = fmaf(aw.x, x, a0); a1 = fmaf(aw.y, x, a1);
            a2 = fmaf(aw.z, x, a2); a3 = fmaf(aw.w, x, a3);
        }
        sm[OFF_PART + w * 128 +       l] = a0;
        sm[OFF_PART + w * 128 +  32 + l] = a1;
        sm[OFF_PART + w * 128 +  64 + l] = a2;
        sm[OFF_PART + w * 128 +  96 + l] = a3;
    }
    __syncthreads();

    // ---- softmax (warps 0..3, head = w) ----
    if (w < 4) {
        float s = 0.f;
        #pragma unroll
        for (int ww = 0; ww < 8; ww++) s += sm[OFF_PART + ww * 128 + w * 32 + l];
        float mx = s;
        #pragma unroll
        for (int d = 16; d; d >>= 1) mx = fmaxf(mx, __shfl_xor_sync(~0u, mx, d));
        float e = expf(s - mx);
        float den = e;
        #pragma unroll
        for (int d = 16; d; d >>= 1) den += __shfl_xor_sync(~0u, den, d);
        sm[OFF_ATT + w * 32 + l] = e / den;
    }
    __syncthreads();

    // ---- new_features partials ----
    {
        int h = w & 3;
        float4 a0 = *(const float4*)(sm + OFF_ATT + h * 32 + n_base);
        float at[4] = {a0.x, a0.y, a0.z, a0.w};
        float s[8];
        #pragma unroll
        for (int i = 0; i < 8; i++) {
            float a = 0.f;
            #pragma unroll
            for (int j = 0; j < 4; j++) a = fmaf(val_f[i][j], at[j], a);
            s[i] = a;
        }
        #pragma unroll
        for (int i = 0; i < 8; i++) {
            #pragma unroll
            for (int d = 8; d <= 16; d <<= 1) s[i] += __shfl_xor_sync(~0u, s[i], d);
        }
        if (ng == 0) {
            int hb = (w >> 2) * 256;
            *(float4*)(sm + OFF_NFH + hb + o_base)     = make_float4(s[0], s[1], s[2], s[3]);
            *(float4*)(sm + OFF_NFH + hb + o_base + 4) = make_float4(s[4], s[5], s[6], s[7]);
        }
    }
    __syncthreads();
    {
        float nf = sm[OFF_NFH + tid] + sm[OFF_NFH + 256 + tid];
        sm[OFF_NF + tid] = nf;
        out[(size_t)m * OD + tid] = nf;
    }
    __syncthreads();

    // ---- gate hidden (packed 4-c weights) ----
    {
        int t = tid & 127;
        float acc1 = (tid >= 128) ? __ldg(rb1 + t) : __ldg(cb1 + t);
        const float4* gw = (const float4*)g_gate4;
        #pragma unroll 4
        for (int c4 = 0; c4 < 64; c4++) {
            float4 wv = __ldg(gw + c4 * 256 + tid);
            float4 nf4 = *(const float4*)(sm + OFF_NF + c4 * 4);
            acc1 = fmaf(nf4.x, wv.x, fmaf(nf4.y, wv.y,
                   fmaf(nf4.z, wv.z, fmaf(nf4.w, wv.w, acc1))));
        }
        sm[OFF_HID + tid] = fmaxf(acc1, 0.f);
    }
    __syncthreads();
    if (w < 2) {
        const float* hid = sm + OFF_HID + w * 128;
        const float* w2v = w ? rw2 : cw2;
        float s = 0.f;
        #pragma unroll
        for (int k = 0; k < 4; k++)
            s = fmaf(hid[l + 32 * k], __ldg(w2v + l + 32 * k), s);
        #pragma unroll
        for (int d = 16; d; d >>= 1) s += __shfl_xor_sync(~0u, s, d);
        if (l == 0) sm[OFF_MISC + 4 + w] = sigf(s + __ldg(w ? rb2 : cb2));
    }
    __syncthreads();
    {
        float nf = sm[OFF_NF + tid];
        out[(size_t)MQ * OD + (size_t)m * OD + tid]     = nf * sm[OFF_MISC + 4];
        out[(size_t)2 * MQ * OD + (size_t)m * OD + tid] = nf * sm[OFF_MISC + 5];
    }
}

// ---------------- launch ------------------------------------------------------
extern "C" void kernel_launch(void* const* d_in, const int* in_sizes, int n_in,
                              void* d_out, int out_size) {
    const float* xyz   = (const float*)d_in[0];
    const float* nxyz  = (const float*)d_in[1];
    const float* feats = (const float*)d_in[2];
    const float* pos_w = (const float*)d_in[3];
    const float* key_w = (const float*)d_in[4];
    const float* v1w   = (const float*)d_in[5];
    const float* bn1g  = (const float*)d_in[6];
    const float* bn1b  = (const float*)d_in[7];
    const float* v2w   = (const float*)d_in[8];
    const float* bn2g  = (const float*)d_in[9];
    const float* bn2b  = (const float*)d_in[10];
    const float* attnw = (const float*)d_in[11];
    const float* kcw   = (const float*)d_in[12];
    const float* qcw   = (const float*)d_in[13];
    const float* qkcw  = (const float*)d_in[14];
    const float* vcw   = (const float*)d_in[15];
    const float* cw1   = (const float*)d_in[16];
    const float* cb1   = (const float*)d_in[17];
    const float* cw2   = (const float*)d_in[18];
    const float* cb2   = (const float*)d_in[19];
    const float* rw1   = (const float*)d_in[20];
    const float* rb1   = (const float*)d_in[21];
    const float* rw2   = (const float*)d_in[22];
    const float* rb2   = (const float*)d_in[23];
    float* out = (float*)d_out;

    static bool attr_set = false;
    if (!attr_set) {
        cudaFuncSetAttribute(main_kernel, cudaFuncAttributeMaxDynamicSharedMemorySize,
                             SM_FLOATS * 4);
        attr_set = true;
    }

    wprep_kernel<<<256, 256>>>(key_w, v1w, v2w, kcw, qcw, qkcw, vcw, cw1, rw1);
    tfeat_kernel<<<dim3(256, 4, 2), dim3(32, 8)>>>(feats);
    ball_kernel<<<MQ / 8, 256>>>(xyz, nxyz);
    main_kernel<<<MQ, 256, SM_FLOATS * 4>>>(xyz, nxyz, pos_w, bn1g, bn1b, bn2g, bn2b,
                                            attnw, cb1, cw2, cb2, rb1, rw2, rb2, out);
}

// round 15
// speedup vs baseline: 1.4431x; 1.4431x over previous
#include <cuda_runtime.h>
#include <cstdint>

typedef unsigned long long ull;

#define NPTS 16384
#define NPER 8192
#define MQ   4096
#define OD   256
#define CG   131
#define CGP  132

// ---------------- device scratch ---------------------------------------------
__device__ float g_featsT[NPTS * 128];        // [point][channel]
__device__ float g_keyT[(CG + 8) * OD];       // [c][o], zero-padded rows
__device__ float g_v1T [(CG + 8) * OD];
__device__ float g_v2T [(OD + 8) * OD];
__device__ float g_ctx4[(OD + 1) * OD * 4];   // [c][o][{vc,qc,kc,qkc}], +1 pad row
__device__ float g_gate4[64 * 256 * 4];       // [c4][col(cls|reg)][4 c]
__device__ int   g_idx [MQ * 32];

// ---------------- packed fp32x2 helpers --------------------------------------
__device__ __forceinline__ void ffma2(ull& d, ull a, ull b) {
    asm("fma.rn.f32x2 %0, %1, %2, %0;" : "+l"(d) : "l"(a), "l"(b));
}
__device__ __forceinline__ ull pack2(float x) {
    ull r; unsigned xi = __float_as_uint(x);
    asm("mov.b64 %0, {%1, %2};" : "=l"(r) : "r"(xi), "r"(xi));
    return r;
}
__device__ __forceinline__ float2 unpack2(ull v) {
    unsigned lo, hi;
    asm("mov.b64 {%0, %1}, %2;" : "=r"(lo), "=r"(hi) : "l"(v));
    return make_float2(__uint_as_float(lo), __uint_as_float(hi));
}
__device__ __forceinline__ float sigf(float x) { return 1.f / (1.f + expf(-x)); }

// ---------------- weight prep ------------------------------------------------
__global__ void wprep_kernel(const float* __restrict__ key_w, const float* __restrict__ v1w,
                             const float* __restrict__ v2w,  const float* __restrict__ kcw,
                             const float* __restrict__ qcw,  const float* __restrict__ qkcw,
                             const float* __restrict__ vcw,  const float* __restrict__ cw1,
                             const float* __restrict__ rw1) {
    int i = blockIdx.x * 256 + threadIdx.x;
    if (i < OD * OD) {
        int c = i >> 8, o = i & 255;
        g_v2T[i] = v2w[o * OD + c];
        float4 cv = make_float4(vcw[o * OD + c], qcw[o * OD + c],
                                kcw[o * OD + c], qkcw[o * OD + c]);
        *(float4*)(g_ctx4 + (size_t)i * 4) = cv;
    }
    if (i < CG * OD) {
        int c = i >> 8, o = i & 255;
        g_keyT[i] = key_w[o * CG + c];
        g_v1T[i]  = v1w[o * CG + c];
    }
    if (i < 64 * 256) {
        int c4 = i >> 8, col = i & 255;
        const float* src = (col < 128) ? cw1 : rw1;
        int t = col & 127;
        float4 v = make_float4(src[t * OD + c4 * 4],     src[t * OD + c4 * 4 + 1],
                               src[t * OD + c4 * 4 + 2], src[t * OD + c4 * 4 + 3]);
        *(float4*)(g_gate4 + (size_t)i * 4) = v;
    }
}

// ---------------- feature transpose ------------------------------------------
__global__ void tfeat_kernel(const float* __restrict__ f) {
    __shared__ float t[32][33];
    int b = blockIdx.z, ct = blockIdx.y * 32, nt = blockIdx.x * 32;
    int x = threadIdx.x, y = threadIdx.y;
    #pragma unroll
    for (int r = 0; r < 32; r += 8)
        t[y + r][x] = f[((size_t)(b * 128 + ct + y + r)) * NPER + nt + x];
    __syncthreads();
    #pragma unroll
    for (int r = 0; r < 32; r += 8)
        g_featsT[(size_t)(b * NPER + nt + y + r) * 128 + ct + x] = t[x][y + r];
}

// ---------------- ball query -------------------------------------------------
__global__ __launch_bounds__(256) void ball_kernel(const float* __restrict__ xyz,
                                                   const float* __restrict__ nxyz) {
    __shared__ int sbuf[8][32];
    int warp = threadIdx.x >> 5, lane = threadIdx.x & 31;
    int m = blockIdx.x * 8 + warp;
    float r2 = __fmul_rn(1.6f, 1.6f);
    float qx = nxyz[m * 3 + 0], qy = nxyz[m * 3 + 1], qz = nxyz[m * 3 + 2];
    int count = 0;
    for (int base = 0; base < NPTS; base += 32) {
        int p = base + lane;
        float dx = __fadd_rn(xyz[p * 3 + 0], -qx);
        float dy = __fadd_rn(xyz[p * 3 + 1], -qy);
        float dz = __fadd_rn(xyz[p * 3 + 2], -qz);
        float d2 = __fadd_rn(__fadd_rn(__fmul_rn(dx, dx), __fmul_rn(dy, dy)),
                             __fmul_rn(dz, dz));
        unsigned msk = __ballot_sync(0xffffffffu, d2 < r2);
        int slot = count + __popc(msk & ((1u << lane) - 1u));
        if ((msk >> lane & 1u) && slot < 32) sbuf[warp][slot] = p;
        count += __popc(msk);
        if (count >= 32) break;
    }
    __syncwarp();
    int v = 0;
    if (count > 0) v = (lane < count) ? sbuf[warp][lane] : sbuf[warp][0];
    g_idx[m * 32 + lane] = v;
}

// ---------------- main fused kernel (NQ=2 per CTA) ---------------------------
// smem float offsets
#define OFF_GF0   0        // 132*32
#define OFF_GF1   4224
#define OFF_VB0   8448     // 256*36
#define OFF_VB1   17664
#define OFF_PMH   26880    // q*512 + nh*256 + o
#define OFF_KMH   27904
#define OFF_PKH   28928
#define OFF_MI4   29952    // (q*256+c)*4  {pm,km,pkm,0}
#define OFF_CTX   32000    // q*1024 + kind*256 + o
#define OFF_AWI   34048    // c*4 + h
#define OFF_PART  35072    // q*1024 + wq*128 + r*32 + l
#define OFF_ATT   37120    // q*128 + h*32 + n
#define OFF_NFH   37376    // q*512 + nh*256 + o
#define OFF_NF    38400    // q*256 + o
#define OFF_HID   38912
#define OFF_MISC  39424    // [0..5] q0/q1 xyz, [8..11] gates, ints at +16 (64 idx)
#define SM_FLOATS 39520
#define BNS 0.99999500003749987f

// stage-1 pass: 4o x 4n x 2q per thread, weight ring depth 4, LDS prefetch 1.
__device__ __forceinline__ void pass1(const float* __restrict__ wsrc,
                                      const float* __restrict__ gf0,
                                      const float* __restrict__ gf1,
                                      ull a0[2][4], ull a1[2][4]) {
    const ulonglong2* wb = (const ulonglong2*)wsrc;
    ulonglong2 wr[4];
    #pragma unroll
    for (int i = 0; i < 4; i++) wr[i] = __ldg(wb + i * 64);
    float4 d0 = *(const float4*)gf0;
    float4 d1 = *(const float4*)gf1;
    #pragma unroll 1
    for (int cb = 0; cb < CGP; cb += 4) {
        #pragma unroll
        for (int s = 0; s < 4; s++) {
            int c = cb + s;
            ulonglong2 wc = wr[s];
            wr[s] = __ldg(wb + (c + 4) * 64);
            float4 u0 = d0, u1 = d1;
            d0 = *(const float4*)(gf0 + (c + 1) * 32);
            d1 = *(const float4*)(gf1 + (c + 1) * 32);
            ull b;
            b = pack2(u0.x); ffma2(a0[0][0], wc.x, b); ffma2(a0[1][0], wc.y, b);
            b = pack2(u0.y); ffma2(a0[0][1], wc.x, b); ffma2(a0[1][1], wc.y, b);
            b = pack2(u0.z); ffma2(a0[0][2], wc.x, b); ffma2(a0[1][2], wc.y, b);
            b = pack2(u0.w); ffma2(a0[0][3], wc.x, b); ffma2(a0[1][3], wc.y, b);
            b = pack2(u1.x); ffma2(a1[0][0], wc.x, b); ffma2(a1[1][0], wc.y, b);
            b = pack2(u1.y); ffma2(a1[0][1], wc.x, b); ffma2(a1[1][1], wc.y, b);
            b = pack2(u1.z); ffma2(a1[0][2], wc.x, b); ffma2(a1[1][2], wc.y, b);
            b = pack2(u1.w); ffma2(a1[0][3], wc.x, b); ffma2(a1[1][3], wc.y, b);
        }
    }
}

// epilogue-1 per query: v -> VB, key kept by caller, means partials to smem
__device__ __forceinline__ void epi1q(float* smp, int q, ull acc[2][4],
                                      float key_f[4][4],
                                      const float* __restrict__ bn1g,
                                      const float* __restrict__ bn1b,
                                      const float pf[12],
                                      int o_base, int n_base, int nh, int lane) {
    float4 g1v = __ldg((const float4*)(bn1g + o_base));
    float4 b1v = __ldg((const float4*)(bn1b + o_base));
    float g1[4] = {g1v.x, g1v.y, g1v.z, g1v.w};
    float b1[4] = {b1v.x, b1v.y, b1v.z, b1v.w};
    float v_f[4][4];
    #pragma unroll
    for (int p = 0; p < 2; p++)
        #pragma unroll
        for (int j = 0; j < 4; j++) {
            float2 u = unpack2(acc[p][j]);
            v_f[2 * p][j]     = fmaxf(fmaf(g1[2 * p],     u.x * BNS, b1[2 * p]),     0.f);
            v_f[2 * p + 1][j] = fmaxf(fmaf(g1[2 * p + 1], u.y * BNS, b1[2 * p + 1]), 0.f);
        }
    float* vb = smp + (q ? OFF_VB1 : OFF_VB0);
    #pragma unroll
    for (int i = 0; i < 4; i++)
        *(float4*)(vb + (o_base + i) * 36 + n_base) =
            make_float4(v_f[i][0], v_f[i][1], v_f[i][2], v_f[i][3]);

    const float* gf = smp + (q ? OFF_GF1 : OFF_GF0);
    float4 x0 = *(const float4*)(gf + 0 * 32 + n_base);
    float4 x1 = *(const float4*)(gf + 1 * 32 + n_base);
    float4 x2 = *(const float4*)(gf + 2 * 32 + n_base);
    float gx0[4] = {x0.x, x0.y, x0.z, x0.w};
    float gx1[4] = {x1.x, x1.y, x1.z, x1.w};
    float gx2[4] = {x2.x, x2.y, x2.z, x2.w};
    float ps[4], ks[4], pks[4];
    #pragma unroll
    for (int i = 0; i < 4; i++) {
        float a = 0.f, bm = 0.f, c2 = 0.f;
        #pragma unroll
        for (int j = 0; j < 4; j++) {
            float pn = fmaxf(fmaf(pf[3 * i], gx0[j],
                          fmaf(pf[3 * i + 1], gx1[j], pf[3 * i + 2] * gx2[j])), 0.f);
            a += pn; bm += key_f[i][j]; c2 += pn * key_f[i][j];
        }
        ps[i] = a; ks[i] = bm; pks[i] = c2;
    }
    #pragma unroll
    for (int i = 0; i < 4; i++) {
        #pragma unroll
        for (int d = 8; d <= 16; d <<= 1) {
            ps[i]  += __shfl_xor_sync(~0u, ps[i],  d);
            ks[i]  += __shfl_xor_sync(~0u, ks[i],  d);
            pks[i] += __shfl_xor_sync(~0u, pks[i], d);
        }
    }
    if ((lane >> 3) == 0) {
        int base = q * 512 + nh * 256 + o_base;
        *(float4*)(smp + OFF_PMH + base) = make_float4(ps[0], ps[1], ps[2], ps[3]);
        *(float4*)(smp + OFF_KMH + base) = make_float4(ks[0], ks[1], ks[2], ks[3]);
        *(float4*)(smp + OFF_PKH + base) = make_float4(pks[0], pks[1], pks[2], pks[3]);
    }
}

// epilogue-2 per query: val -> regs, emb -> VB
__device__ __forceinline__ void epi2q(float* smp, int q, ull acc[2][4],
                                      float key_f[4][4], float val_f[4][4],
                                      const float* __restrict__ bn2g,
                                      const float* __restrict__ bn2b,
                                      const float pf[12],
                                      int o_base, int n_base) {
    float4 g2v = __ldg((const float4*)(bn2g + o_base));
    float4 b2v = __ldg((const float4*)(bn2b + o_base));
    float g2[4] = {g2v.x, g2v.y, g2v.z, g2v.w};
    float b2[4] = {b2v.x, b2v.y, b2v.z, b2v.w};
    const float* ctx = smp + OFF_CTX + q * 1024;
    float4 cv = *(const float4*)(ctx + o_base);
    float4 cq = *(const float4*)(ctx + 256 + o_base);
    float4 ck = *(const float4*)(ctx + 512 + o_base);
    float4 cu = *(const float4*)(ctx + 768 + o_base);
    float vc[4]  = {cv.x, cv.y, cv.z, cv.w};
    float qc[4]  = {cq.x, cq.y, cq.z, cq.w};
    float kc[4]  = {ck.x, ck.y, ck.z, ck.w};
    float qkc[4] = {cu.x, cu.y, cu.z, cu.w};
    const float* gf = smp + (q ? OFF_GF1 : OFF_GF0);
    float4 x0 = *(const float4*)(gf + 0 * 32 + n_base);
    float4 x1 = *(const float4*)(gf + 1 * 32 + n_base);
    float4 x2 = *(const float4*)(gf + 2 * 32 + n_base);
    float gx0[4] = {x0.x, x0.y, x0.z, x0.w};
    float gx1[4] = {x1.x, x1.y, x1.z, x1.w};
    float gx2[4] = {x2.x, x2.y, x2.z, x2.w};
    float* vb = smp + (q ? OFF_VB1 : OFF_VB0);
    #pragma unroll
    for (int i = 0; i < 4; i++) {
        float raw[4];
        #pragma unroll
        for (int j = 0; j < 4; j++) {
            float2 u = unpack2(acc[i >> 1][j]);
            raw[j] = (i & 1) ? u.y : u.x;
        }
        float emb[4];
        #pragma unroll
        for (int j = 0; j < 4; j++) {
            float pn = fmaxf(fmaf(pf[3 * i], gx0[j],
                          fmaf(pf[3 * i + 1], gx1[j], pf[3 * i + 2] * gx2[j])), 0.f);
            val_f[i][j] = fmaxf(fmaf(g2[i], raw[j] * BNS, b2[i]), 0.f) + pn * vc[i];
            emb[j] = fmaf(pn, qc[i],
                      fmaf(key_f[i][j], kc[i], (pn * key_f[i][j]) * qkc[i]));
        }
        *(float4*)(vb + (o_base + i) * 36 + n_base) =
            make_float4(emb[0], emb[1], emb[2], emb[3]);
    }
}

__global__ __launch_bounds__(512, 1) void main_kernel(
    const float* __restrict__ xyz,  const float* __restrict__ nxyz,
    const float* __restrict__ pos_w,
    const float* __restrict__ bn1g, const float* __restrict__ bn1b,
    const float* __restrict__ bn2g, const float* __restrict__ bn2b,
    const float* __restrict__ attn_w,
    const float* __restrict__ cb1,  const float* __restrict__ cw2,
    const float* __restrict__ cb2,  const float* __restrict__ rb1,
    const float* __restrict__ rw2,  const float* __restrict__ rb2,
    float* __restrict__ out)
{
    extern __shared__ float sm[];
    const int tid = threadIdx.x;
    const int l = tid & 31, w = tid >> 5;
    int* sidx = (int*)(sm + OFF_MISC + 16);

    // ---- init ----
    if (tid < 64) sidx[tid] = g_idx[blockIdx.x * 64 + tid];
    if (tid >= 64 && tid < 70) sm[OFF_MISC + tid - 64] = nxyz[blockIdx.x * 6 + tid - 64];
    if (tid < 256) {
        #pragma unroll
        for (int h = 0; h < 4; h++)
            sm[OFF_AWI + tid * 4 + h] = __ldg(attn_w + h * 256 + tid);
    } else if (tid < 320) {
        int z = tid - 256, q = z >> 5, n = z & 31;
        sm[(q ? OFF_GF1 : OFF_GF0) + 131 * 32 + n] = 0.f;
    }
    __syncthreads();

    // ---- gather gf per query ----
    {
        int q = tid >> 8, part = (tid >> 5) & 7, n = tid & 31;
        int p = sidx[q * 32 + n];
        const float4* src = (const float4*)(g_featsT + (size_t)p * 128 + part * 16);
        float* gf = sm + (q ? OFF_GF1 : OFF_GF0);
        #pragma unroll
        for (int k = 0; k < 4; k++) {
            float4 v = __ldg(src + k);
            int c = 3 + part * 16 + k * 4;
            gf[c * 32 + n]       = v.x;
            gf[(c + 1) * 32 + n] = v.y;
            gf[(c + 2) * 32 + n] = v.z;
            gf[(c + 3) * 32 + n] = v.w;
        }
        if (part == 0) {
            float qx = sm[OFF_MISC + q * 3], qy = sm[OFF_MISC + q * 3 + 1],
                  qz = sm[OFF_MISC + q * 3 + 2];
            gf[n]      = xyz[p * 3 + 0] - qx;
            gf[32 + n] = xyz[p * 3 + 1] - qy;
            gf[64 + n] = xyz[p * 3 + 2] - qz;
        }
    }
    __syncthreads();

    // tile: 4o x 4n x 2q per thread; 16 warps = 8 o-blocks x 2 n-halves
    const int og = l & 7, ng = l >> 3, nh = w >> 3;
    const int o_base = (w & 7) * 32 + og * 4;
    const int n_base = nh * 16 + ng * 4;
    const float* gf0 = sm + OFF_GF0 + n_base;
    const float* gf1 = sm + OFF_GF1 + n_base;

    float pf[12];
    {
        const float4* pp = (const float4*)(pos_w + o_base * 3);
        float4 p0 = __ldg(pp), p1 = __ldg(pp + 1), p2 = __ldg(pp + 2);
        pf[0] = p0.x; pf[1] = p0.y; pf[2]  = p0.z; pf[3]  = p0.w;
        pf[4] = p1.x; pf[5] = p1.y; pf[6]  = p1.z; pf[7]  = p1.w;
        pf[8] = p2.x; pf[9] = p2.y; pf[10] = p2.z; pf[11] = p2.w;
    }

    ull acc0[2][4], acc1[2][4];
    // ---- pass A: key ----
    #pragma unroll
    for (int i = 0; i < 2; i++)
        #pragma unroll
        for (int j = 0; j < 4; j++) { acc0[i][j] = 0ull; acc1[i][j] = 0ull; }
    pass1(g_keyT + o_base, gf0, gf1, acc0, acc1);
    float key0[4][4], key1[4][4];
    #pragma unroll
    for (int p = 0; p < 2; p++)
        #pragma unroll
        for (int j = 0; j < 4; j++) {
            float2 u0 = unpack2(acc0[p][j]);
            key0[2 * p][j]     = fmaxf(u0.x, 0.f);
            key0[2 * p + 1][j] = fmaxf(u0.y, 0.f);
            float2 u1 = unpack2(acc1[p][j]);
            key1[2 * p][j]     = fmaxf(u1.x, 0.f);
            key1[2 * p + 1][j] = fmaxf(u1.y, 0.f);
        }

    // ---- pass B: val1 ----
    #pragma unroll
    for (int i = 0; i < 2; i++)
        #pragma unroll
        for (int j = 0; j < 4; j++) { acc0[i][j] = 0ull; acc1[i][j] = 0ull; }
    pass1(g_v1T + o_base, gf0, gf1, acc0, acc1);
    epi1q(sm, 0, acc0, key0, bn1g, bn1b, pf, o_base, n_base, nh, l);
    epi1q(sm, 1, acc1, key1, bn1g, bn1b, pf, o_base, n_base, nh, l);
    __syncthreads();

    // ---- combine means ----
    {
        int o = tid & 255, q = tid >> 8;
        int b0 = q * 512 + o;
        float pm = (sm[OFF_PMH + b0] + sm[OFF_PMH + b0 + 256]) * (1.f / 32.f);
        float km = (sm[OFF_KMH + b0] + sm[OFF_KMH + b0 + 256]) * (1.f / 32.f);
        float pk = (sm[OFF_PKH + b0] + sm[OFF_PKH + b0 + 256]) * (1.f / 32.f);
        *(float4*)(sm + OFF_MI4 + (q * 256 + o) * 4) = make_float4(pm, km, pk, 0.f);
    }
    __syncthreads();

    // ---- val2 GEMM fused with ctx matvec ----
    #pragma unroll
    for (int i = 0; i < 2; i++)
        #pragma unroll
        for (int j = 0; j < 4; j++) { acc0[i][j] = 0ull; acc1[i][j] = 0ull; }
    {
        const int o_ctx = tid & 255, q_ctx = tid >> 8;
        const ulonglong2* wb = (const ulonglong2*)(g_v2T + o_base);
        ulonglong2 wr[4];
        #pragma unroll
        for (int i = 0; i < 4; i++) wr[i] = __ldg(wb + i * 64);
        const float* vb0 = sm + OFF_VB0 + n_base;
        const float* vb1 = sm + OFF_VB1 + n_base;
        float4 d0 = *(const float4*)vb0;
        float4 d1 = *(const float4*)vb1;
        const float4* cwp = (const float4*)g_ctx4 + o_ctx;
        float4 cw_n = __ldg(cwp);
        const float4* mip = (const float4*)(sm + OFF_MI4 + q_ctx * 1024);
        float4 mi_n = mip[0];
        float av = 0.f, aq2 = 0.f, ak = 0.f, aqk = 0.f;
        #pragma unroll 1
        for (int cb = 0; cb < OD; cb += 4) {
            #pragma unroll
            for (int s = 0; s < 4; s++) {
                int c = cb + s;
                ulonglong2 wc = wr[s];
                wr[s] = __ldg(wb + (c + 4) * 64);
                float4 u0 = d0, u1 = d1;
                d0 = *(const float4*)(vb0 + (c + 1) * 36);
                d1 = *(const float4*)(vb1 + (c + 1) * 36);
                float4 cwc = cw_n; cw_n = __ldg(cwp + (c + 1) * 256);
                float4 mic = mi_n; mi_n = mip[c + 1];
                av  = fmaf(mic.x, cwc.x, av);
                aq2 = fmaf(mic.x, cwc.y, aq2);
                ak  = fmaf(mic.y, cwc.z, ak);
                aqk = fmaf(mic.z, cwc.w, aqk);
                ull b;
                b = pack2(u0.x); ffma2(acc0[0][0], wc.x, b); ffma2(acc0[1][0], wc.y, b);
                b = pack2(u0.y); ffma2(acc0[0][1], wc.x, b); ffma2(acc0[1][1], wc.y, b);
                b = pack2(u0.z); ffma2(acc0[0][2], wc.x, b); ffma2(acc0[1][2], wc.y, b);
                b = pack2(u0.w); ffma2(acc0[0][3], wc.x, b); ffma2(acc0[1][3], wc.y, b);
                b = pack2(u1.x); ffma2(acc1[0][0], wc.x, b); ffma2(acc1[1][0], wc.y, b);
                b = pack2(u1.y); ffma2(acc1[0][1], wc.x, b); ffma2(acc1[1][1], wc.y, b);
                b = pack2(u1.z); ffma2(acc1[0][2], wc.x, b); ffma2(acc1[1][2], wc.y, b);
                b = pack2(u1.w); ffma2(acc1[0][3], wc.x, b); ffma2(acc1[1][3], wc.y, b);
            }
        }
        float* ctx = sm + OFF_CTX + q_ctx * 1024;
        ctx[o_ctx]       = sigf(av);
        ctx[256 + o_ctx] = sigf(aq2);
        ctx[512 + o_ctx] = sigf(ak);
        ctx[768 + o_ctx] = sigf(aqk);
    }
    __syncthreads();   // VB reads done, CTX visible

    // ---- epilogue 2 ----
    float val0[4][4], val1[4][4];
    epi2q(sm, 0, acc0, key0, val0, bn2g, bn2b, pf, o_base, n_base);
    epi2q(sm, 1, acc1, key1, val1, bn2g, bn2b, pf, o_base, n_base);
    __syncthreads();

    // ---- logits partials ----
    {
        int q = w >> 3, wq = w & 7;
        const float* vb = sm + (q ? OFF_VB1 : OFF_VB0);
        float s0 = 0.f, s1 = 0.f, s2 = 0.f, s3 = 0.f;
        #pragma unroll 4
        for (int c = wq * 32; c < wq * 32 + 32; c++) {
            float x = vb[c * 36 + l];
            float4 aw = *(const float4*)(sm + OFF_AWI + c * 4);
            s0 = fmaf(aw.x, x, s0); s1 = fmaf(aw.y, x, s1);
            s2 = fmaf(aw.z, x, s2); s3 = fmaf(aw.w, x, s3);
        }
        float* part = sm + OFF_PART + q * 1024 + wq * 128;
        part[l] = s0; part[32 + l] = s1; part[64 + l] = s2; part[96 + l] = s3;
    }
    __syncthreads();

    // ---- softmax ----
    if ((w & 7) < 4) {
        int q = w >> 3, h = w & 3;
        float s = 0.f;
        #pragma unroll
        for (int ww = 0; ww < 8; ww++)
            s += sm[OFF_PART + q * 1024 + ww * 128 + h * 32 + l];
        float mx = s;
        #pragma unroll
        for (int d = 16; d; d >>= 1) mx = fmaxf(mx, __shfl_xor_sync(~0u, mx, d));
        float e = expf(s - mx);
        float den = e;
        #pragma unroll
        for (int d = 16; d; d >>= 1) den += __shfl_xor_sync(~0u, den, d);
        sm[OFF_ATT + q * 128 + h * 32 + l] = e / den;
    }
    __syncthreads();

    // ---- new_features partials (both queries) ----
    {
        int h = (w & 7) >> 1;   // o_base>>6 = ((w&7)*32 + og*4)>>6 = (w&7)>>1
        #pragma unroll
        for (int q = 0; q < 2; q++) {
            float4 a4 = *(const float4*)(sm + OFF_ATT + q * 128 + h * 32 + n_base);
            float at[4] = {a4.x, a4.y, a4.z, a4.w};
            float s[4];
            #pragma unroll
            for (int i = 0; i < 4; i++) {
                float a = 0.f;
                #pragma unroll
                for (int j = 0; j < 4; j++)
                    a = fmaf(q ? val1[i][j] : val0[i][j], at[j], a);
                s[i] = a;
            }
            #pragma unroll
            for (int i = 0; i < 4; i++) {
                #pragma unroll
                for (int d = 8; d <= 16; d <<= 1) s[i] += __shfl_xor_sync(~0u, s[i], d);
            }
            if (ng == 0)
                *(float4*)(sm + OFF_NFH + q * 512 + nh * 256 + o_base) =
                    make_float4(s[0], s[1], s[2], s[3]);
        }
    }
    __syncthreads();
    {
        int o = tid & 255, q = tid >> 8;
        float nf = sm[OFF_NFH + q * 512 + o] + sm[OFF_NFH + q * 512 + 256 + o];
        sm[OFF_NF + q * 256 + o] = nf;
        out[(size_t)(blockIdx.x * 2 + q) * OD + o] = nf;
    }
    __syncthreads();

    // ---- gate hidden ----
    {
        int col = tid & 255, q = tid >> 8;
        int t = col & 127;
        float a = (col >= 128) ? __ldg(rb1 + t) : __ldg(cb1 + t);
        const float4* gw = (const float4*)g_gate4;
        const float* nfq = sm + OFF_NF + q * 256;
        #pragma unroll 4
        for (int c4 = 0; c4 < 64; c4++) {
            float4 wv = __ldg(gw + c4 * 256 + col);
            float4 nf4 = *(const float4*)(nfq + c4 * 4);
            a = fmaf(nf4.x, wv.x, fmaf(nf4.y, wv.y,
                fmaf(nf4.z, wv.z, fmaf(nf4.w, wv.w, a))));
        }
        sm[OFF_HID + q * 256 + col] = fmaxf(a, 0.f);
    }
    __syncthreads();
    if ((w & 7) < 2) {
        int q = w >> 3, wq = w & 7;
        const float* hid = sm + OFF_HID + q * 256 + wq * 128;
        const float* w2v = wq ? rw2 : cw2;
        float s = 0.f;
        #pragma unroll
        for (int k = 0; k < 4; k++)
            s = fmaf(hid[l + 32 * k], __ldg(w2v + l + 32 * k), s);
        #pragma unroll
        for (int d = 16; d; d >>= 1) s += __shfl_xor_sync(~0u, s, d);
        if (l == 0) sm[OFF_MISC + 8 + q * 2 + wq] = sigf(s + __ldg(wq ? rb2 : cb2));
    }
    __syncthreads();
    {
        int o = tid & 255, q = tid >> 8;
        float nf = sm[OFF_NF + q * 256 + o];
        size_t mrow = (size_t)(blockIdx.x * 2 + q) * OD + o;
        out[(size_t)MQ * OD + mrow]     = nf * sm[OFF_MISC + 8 + q * 2];
        out[(size_t)2 * MQ * OD + mrow] = nf * sm[OFF_MISC + 8 + q * 2 + 1];
    }
}

// ---------------- launch ------------------------------------------------------
extern "C" void kernel_launch(void* const* d_in, const int* in_sizes, int n_in,
                              void* d_out, int out_size) {
    const float* xyz   = (const float*)d_in[0];
    const float* nxyz  = (const float*)d_in[1];
    const float* feats = (const float*)d_in[2];
    const float* pos_w = (const float*)d_in[3];
    const float* key_w = (const float*)d_in[4];
    const float* v1w   = (const float*)d_in[5];
    const float* bn1g  = (const float*)d_in[6];
    const float* bn1b  = (const float*)d_in[7];
    const float* v2w   = (const float*)d_in[8];
    const float* bn2g  = (const float*)d_in[9];
    const float* bn2b  = (const float*)d_in[10];
    const float* attnw = (const float*)d_in[11];
    const float* kcw   = (const float*)d_in[12];
    const float* qcw   = (const float*)d_in[13];
    const float* qkcw  = (const float*)d_in[14];
    const float* vcw   = (const float*)d_in[15];
    const float* cw1   = (const float*)d_in[16];
    const float* cb1   = (const float*)d_in[17];
    const float* cw2   = (const float*)d_in[18];
    const float* cb2   = (const float*)d_in[19];
    const float* rw1   = (const float*)d_in[20];
    const float* rb1   = (const float*)d_in[21];
    const float* rw2   = (const float*)d_in[22];
    const float* rb2   = (const float*)d_in[23];
    float* out = (float*)d_out;

    static bool attr_set = false;
    if (!attr_set) {
        cudaFuncSetAttribute(main_kernel, cudaFuncAttributeMaxDynamicSharedMemorySize,
                             SM_FLOATS * 4);
        attr_set = true;
    }

    wprep_kernel<<<256, 256>>>(key_w, v1w, v2w, kcw, qcw, qkcw, vcw, cw1, rw1);
    tfeat_kernel<<<dim3(256, 4, 2), dim3(32, 8)>>>(feats);
    ball_kernel<<<MQ / 8, 256>>>(xyz, nxyz);
    main_kernel<<<MQ / 2, 512, SM_FLOATS * 4>>>(xyz, nxyz, pos_w, bn1g, bn1b, bn2g, bn2b,
                                                attnw, cb1, cw2, cb2, rb1, rw2, rb2, out);
}